// round 1
// baseline (speedup 1.0000x reference)
#include <cuda_runtime.h>
#include <cuda_bf16.h>
#include <math.h>

// ============================================================================
// StandardAttention: out = softmax_causal((xWq^T)(xWk^T)^T / sqrt(dh)) (xWv^T) Wo^T
// B=4, S=2048, D_MODEL=2048, H=16, Dh=128. All fp32.
//
// Stage 1: 3x GEMM-NT  [8192,2048] @ [2048,2048]^T -> Q,K,V (head-interleaved
//          layout [b, s, h*128+d], which is the natural GEMM output layout)
// Stage 2: flash-attention (causal, online softmax), BM=BN=64, Dh=128
// Stage 3: GEMM-NT  attn_out @ Wo^T -> out
// ============================================================================

#define D_MODEL 2048
#define SEQ     2048
#define BATCH   4
#define NHEADS  16
#define DHEAD   128
#define MROWS   (BATCH * SEQ)          // 8192

// 64 MB scratch each (sanctioned: __device__ globals for scratch)
__device__ float g_Q [ (size_t)BATCH * SEQ * D_MODEL ];
__device__ float g_K [ (size_t)BATCH * SEQ * D_MODEL ];
__device__ float g_V [ (size_t)BATCH * SEQ * D_MODEL ];
__device__ float g_AO[ (size_t)BATCH * SEQ * D_MODEL ];

// ----------------------------------------------------------------------------
// GEMM-NT: C[M,N] = A[M,K] * B[N,K]^T, all row-major, M,N,K multiples of 128/8.
// 128x128 block tile, K-step 8, 256 threads, 8x8 per-thread microtile.
// ----------------------------------------------------------------------------
__global__ void __launch_bounds__(256) gemm_nt_kernel(
    const float* __restrict__ A, const float* __restrict__ B,
    float* __restrict__ C, int M, int N, int K)
{
    __shared__ float As[8][132];   // transposed tile, padded: conflict-free
    __shared__ float Bs[8][132];

    const int t    = threadIdx.x;
    const int bm   = blockIdx.y * 128;
    const int bn   = blockIdx.x * 128;
    const int lrow = t >> 1;             // 0..127
    const int lcol = (t & 1) << 2;       // 0 or 4
    const int tx   = t & 15;             // 0..15
    const int ty   = t >> 4;             // 0..15

    const float* Ap = A + (size_t)(bm + lrow) * K + lcol;
    const float* Bp = B + (size_t)(bn + lrow) * K + lcol;

    float acc[8][8];
#pragma unroll
    for (int i = 0; i < 8; i++)
#pragma unroll
        for (int j = 0; j < 8; j++) acc[i][j] = 0.0f;

    for (int k0 = 0; k0 < K; k0 += 8) {
        const float4 av = *(const float4*)(Ap + k0);
        const float4 bv = *(const float4*)(Bp + k0);
        __syncthreads();   // previous iteration's compute reads done
        As[lcol + 0][lrow] = av.x;
        As[lcol + 1][lrow] = av.y;
        As[lcol + 2][lrow] = av.z;
        As[lcol + 3][lrow] = av.w;
        Bs[lcol + 0][lrow] = bv.x;
        Bs[lcol + 1][lrow] = bv.y;
        Bs[lcol + 2][lrow] = bv.z;
        Bs[lcol + 3][lrow] = bv.w;
        __syncthreads();

#pragma unroll
        for (int kk = 0; kk < 8; kk++) {
            const float4 a0 = *(const float4*)&As[kk][ty * 4];
            const float4 a1 = *(const float4*)&As[kk][64 + ty * 4];
            const float4 b0 = *(const float4*)&Bs[kk][tx * 4];
            const float4 b1 = *(const float4*)&Bs[kk][64 + tx * 4];
            const float a[8] = {a0.x, a0.y, a0.z, a0.w, a1.x, a1.y, a1.z, a1.w};
            const float b[8] = {b0.x, b0.y, b0.z, b0.w, b1.x, b1.y, b1.z, b1.w};
#pragma unroll
            for (int i = 0; i < 8; i++)
#pragma unroll
                for (int j = 0; j < 8; j++)
                    acc[i][j] += a[i] * b[j];
        }
    }

#pragma unroll
    for (int i = 0; i < 8; i++) {
        const int row = bm + ((i < 4) ? (ty * 4 + i) : (64 + ty * 4 + (i - 4)));
        float* Crow = C + (size_t)row * N + bn;
        float4 v0 = make_float4(acc[i][0], acc[i][1], acc[i][2], acc[i][3]);
        float4 v1 = make_float4(acc[i][4], acc[i][5], acc[i][6], acc[i][7]);
        *(float4*)(Crow + tx * 4)      = v0;
        *(float4*)(Crow + 64 + tx * 4) = v1;
    }
}

// ----------------------------------------------------------------------------
// Flash attention (causal). One block = 64 query rows of one (b,h).
// 256 threads = 8 warps; warp w owns query rows w*8..w*8+7.
// Lane l owns key cols {l, 32+l} of the 64-wide key tile, and output
// dims {4l..4l+3} of the 128-wide head dim.
// ----------------------------------------------------------------------------
#define QS_STRIDE 128
#define KS_STRIDE 132
#define VS_STRIDE 132
#define PS_STRIDE 66
#define SM_QS 0
#define SM_KS (SM_QS + 64 * QS_STRIDE)
#define SM_VS (SM_KS + 64 * KS_STRIDE)
#define SM_PS (SM_VS + 64 * VS_STRIDE)
#define ATT_SMEM_FLOATS (SM_PS + 64 * PS_STRIDE)
#define ATT_SMEM_BYTES  (ATT_SMEM_FLOATS * 4)
#define NEG_BIG (-1.0e30f)

__global__ void __launch_bounds__(256) attn_kernel(
    const float* __restrict__ Q, const float* __restrict__ K,
    const float* __restrict__ V, float* __restrict__ O)
{
    extern __shared__ float sm[];
    float* Qs = sm + SM_QS;
    float* Ks = sm + SM_KS;
    float* Vs = sm + SM_VS;
    float* Ps = sm + SM_PS;

    const int t  = threadIdx.x;
    const int w  = t >> 5;
    const int l  = t & 31;
    const int bh = blockIdx.y;                 // b*16 + h
    const int b  = bh >> 4;
    const int h  = bh & 15;
    const int mt = blockIdx.x;                 // query tile index (64 rows)
    const size_t base = ((size_t)b * SEQ) * D_MODEL + (size_t)h * DHEAD;
    const float scale = 0.088388347648318447f; // 1/sqrt(128)

    // Load Q tile (64 x 128): 2048 float4, 8 per thread.
#pragma unroll
    for (int it = 0; it < 8; it++) {
        const int i  = it * 256 + t;
        const int r  = i >> 5;
        const int c4 = (i & 31) * 4;
        *(float4*)&Qs[r * QS_STRIDE + c4] =
            *(const float4*)(Q + base + (size_t)(mt * 64 + r) * D_MODEL + c4);
    }

    float m_i[8], l_i[8], acc[8][4];
#pragma unroll
    for (int i = 0; i < 8; i++) {
        m_i[i] = NEG_BIG; l_i[i] = 0.0f;
        acc[i][0] = acc[i][1] = acc[i][2] = acc[i][3] = 0.0f;
    }

    const int r0 = w * 8;

    for (int nt = 0; nt <= mt; nt++) {
        __syncthreads();   // previous tile's Ks/Vs reads done (and Q load on nt=0)
        // Load K,V tiles (64 x 128 each)
#pragma unroll
        for (int it = 0; it < 8; it++) {
            const int i  = it * 256 + t;
            const int r  = i >> 5;
            const int c4 = (i & 31) * 4;
            const size_t goff = base + (size_t)(nt * 64 + r) * D_MODEL + c4;
            *(float4*)&Ks[r * KS_STRIDE + c4] = *(const float4*)(K + goff);
            *(float4*)&Vs[r * VS_STRIDE + c4] = *(const float4*)(V + goff);
        }
        __syncthreads();

        // S = Q K^T (per lane: 8 rows x 2 cols)
        float s0[8], s1[8];
#pragma unroll
        for (int i = 0; i < 8; i++) { s0[i] = 0.0f; s1[i] = 0.0f; }
#pragma unroll 4
        for (int k4 = 0; k4 < 32; k4++) {
            const float4 kv0 = *(const float4*)&Ks[l * KS_STRIDE + k4 * 4];
            const float4 kv1 = *(const float4*)&Ks[(32 + l) * KS_STRIDE + k4 * 4];
#pragma unroll
            for (int i = 0; i < 8; i++) {
                const float4 qv = *(const float4*)&Qs[(r0 + i) * QS_STRIDE + k4 * 4];
                s0[i] += qv.x * kv0.x + qv.y * kv0.y + qv.z * kv0.z + qv.w * kv0.w;
                s1[i] += qv.x * kv1.x + qv.y * kv1.y + qv.z * kv1.z + qv.w * kv1.w;
            }
        }

        const bool diag = (nt == mt);
        // Online softmax per row
#pragma unroll
        for (int i = 0; i < 8; i++) {
            const int qg = mt * 64 + r0 + i;
            float sv0 = s0[i] * scale;
            float sv1 = s1[i] * scale;
            if (diag) {
                if (nt * 64 + l      > qg) sv0 = NEG_BIG;
                if (nt * 64 + 32 + l > qg) sv1 = NEG_BIG;
            }
            float mx = fmaxf(sv0, sv1);
#pragma unroll
            for (int off = 16; off > 0; off >>= 1)
                mx = fmaxf(mx, __shfl_xor_sync(0xffffffffu, mx, off));
            const float mnew  = fmaxf(m_i[i], mx);
            const float alpha = __expf(m_i[i] - mnew);
            const float p0 = __expf(sv0 - mnew);
            const float p1 = __expf(sv1 - mnew);
            float rs = p0 + p1;
#pragma unroll
            for (int off = 16; off > 0; off >>= 1)
                rs += __shfl_xor_sync(0xffffffffu, rs, off);
            l_i[i] = l_i[i] * alpha + rs;
            m_i[i] = mnew;
            acc[i][0] *= alpha; acc[i][1] *= alpha;
            acc[i][2] *= alpha; acc[i][3] *= alpha;
            Ps[(r0 + i) * PS_STRIDE + l]      = p0;
            Ps[(r0 + i) * PS_STRIDE + 32 + l] = p1;
        }
        __syncwarp();   // P is warp-private: warp-level RAW only

        // O += P V  (per lane: 8 rows x 4 dims, dims 4l..4l+3)
#pragma unroll 4
        for (int c = 0; c < 64; c++) {
            const float4 vv = *(const float4*)&Vs[c * VS_STRIDE + l * 4];
#pragma unroll
            for (int i = 0; i < 8; i++) {
                const float p = Ps[(r0 + i) * PS_STRIDE + c];
                acc[i][0] += p * vv.x;
                acc[i][1] += p * vv.y;
                acc[i][2] += p * vv.z;
                acc[i][3] += p * vv.w;
            }
        }
        __syncwarp();   // P reads done before next tile overwrites
    }

    // Epilogue: normalize and store
#pragma unroll
    for (int i = 0; i < 8; i++) {
        const float inv = 1.0f / l_i[i];
        const int qg = mt * 64 + r0 + i;
        float4 o = make_float4(acc[i][0] * inv, acc[i][1] * inv,
                               acc[i][2] * inv, acc[i][3] * inv);
        *(float4*)(O + base + (size_t)qg * D_MODEL + l * 4) = o;
    }
}

// ----------------------------------------------------------------------------
// Launcher
// ----------------------------------------------------------------------------
extern "C" void kernel_launch(void* const* d_in, const int* in_sizes, int n_in,
                              void* d_out, int out_size)
{
    const float* x  = (const float*)d_in[0];
    const float* Wq = (const float*)d_in[1];
    const float* Wk = (const float*)d_in[2];
    const float* Wv = (const float*)d_in[3];
    const float* Wo = (const float*)d_in[4];
    float* out = (float*)d_out;

    void *pQ, *pK, *pV, *pA;
    cudaGetSymbolAddress(&pQ, g_Q);
    cudaGetSymbolAddress(&pK, g_K);
    cudaGetSymbolAddress(&pV, g_V);
    cudaGetSymbolAddress(&pA, g_AO);

    cudaFuncSetAttribute(attn_kernel,
                         cudaFuncAttributeMaxDynamicSharedMemorySize,
                         ATT_SMEM_BYTES);

    const dim3 gemm_grid(D_MODEL / 128, MROWS / 128);   // (16, 64)
    gemm_nt_kernel<<<gemm_grid, 256>>>(x, Wq, (float*)pQ, MROWS, D_MODEL, D_MODEL);
    gemm_nt_kernel<<<gemm_grid, 256>>>(x, Wk, (float*)pK, MROWS, D_MODEL, D_MODEL);
    gemm_nt_kernel<<<gemm_grid, 256>>>(x, Wv, (float*)pV, MROWS, D_MODEL, D_MODEL);

    const dim3 attn_grid(SEQ / 64, BATCH * NHEADS);     // (32, 64)
    attn_kernel<<<attn_grid, 256, ATT_SMEM_BYTES>>>(
        (const float*)pQ, (const float*)pK, (const float*)pV, (float*)pA);

    gemm_nt_kernel<<<gemm_grid, 256>>>((const float*)pA, Wo, out,
                                       MROWS, D_MODEL, D_MODEL);
}

// round 4
// speedup vs baseline: 1.6794x; 1.6794x over previous
#include <cuda_runtime.h>
#include <cuda_bf16.h>
#include <cstdint>
#include <math.h>

// ============================================================================
// StandardAttention, B=4, S=2048, D=2048, H=16, Dh=128, fp32.
// R4: projections via bf16x3 split-precision mma.sync.m16n8k16 (fp32-accurate:
//     hi*hi + lo*hi + hi*lo, rn splits -> ~2^-18 per-product error).
//     R3's raw-tf32 feed was RZ-biased 2^-11 -> 2.75e-3 rel_err (failed).
// Attention: SIMT flash kernel (unchanged from R1).
// ============================================================================

#define D_MODEL 2048
#define SEQ     2048
#define BATCH   4
#define NHEADS  16
#define DHEAD   128
#define MROWS   (BATCH * SEQ)          // 8192

__device__ float g_Q [ (size_t)BATCH * SEQ * D_MODEL ];
__device__ float g_K [ (size_t)BATCH * SEQ * D_MODEL ];
__device__ float g_V [ (size_t)BATCH * SEQ * D_MODEL ];
__device__ float g_AO[ (size_t)BATCH * SEQ * D_MODEL ];

// ---------------------------------------------------------------------------
// Helpers
// ---------------------------------------------------------------------------
__device__ __forceinline__ uint32_t smem_u32(const void* p) {
    uint32_t a;
    asm("{ .reg .u64 t; cvta.to.shared.u64 t, %1; cvt.u32.u64 %0, t; }"
        : "=r"(a) : "l"(p));
    return a;
}
__device__ __forceinline__ void cp_async16(uint32_t dst, const void* src) {
    asm volatile("cp.async.cg.shared.global [%0], [%1], 16;"
                 :: "r"(dst), "l"(src) : "memory");
}
__device__ __forceinline__ void cp_commit() {
    asm volatile("cp.async.commit_group;" ::: "memory");
}
template<int N> __device__ __forceinline__ void cp_wait() {
    asm volatile("cp.async.wait_group %0;" :: "n"(N) : "memory");
}

// bf16 m16n8k16 MMA, fp32 accumulate
__device__ __forceinline__ void mma_bf16(float* d, const uint32_t* a,
                                         const uint32_t* b) {
    asm volatile(
        "mma.sync.aligned.m16n8k16.row.col.f32.bf16.bf16.f32 "
        "{%0,%1,%2,%3}, {%4,%5,%6,%7}, {%8,%9}, {%0,%1,%2,%3};"
        : "+f"(d[0]), "+f"(d[1]), "+f"(d[2]), "+f"(d[3])
        : "r"(a[0]), "r"(a[1]), "r"(a[2]), "r"(a[3]), "r"(b[0]), "r"(b[1]));
}

// Split a float2 into packed-bf16 hi pair and lo pair (rn both levels).
// Packed reg: lower half = .x (even k), upper half = .y (odd k).
__device__ __forceinline__ void split2(float2 v, uint32_t& hi, uint32_t& lo) {
    asm("cvt.rn.bf16x2.f32 %0, %1, %2;" : "=r"(hi) : "f"(v.y), "f"(v.x));
    const float hx = __uint_as_float(hi << 16);
    const float hy = __uint_as_float(hi & 0xffff0000u);
    const float lx = v.x - hx;
    const float ly = v.y - hy;
    asm("cvt.rn.bf16x2.f32 %0, %1, %2;" : "=r"(lo) : "f"(ly), "f"(lx));
}

// ---------------------------------------------------------------------------
// bf16x3 GEMM-NT: C[8192,2048] = A[8192,2048] * B[2048,2048]^T (fp32 I/O)
// CTA 128x256, BK=32, 3-stage cp.async. 8 warps, warp tile 64x64.
// Smem rows padded to 40 floats -> float2 fragment LDS is conflict-free
// (bank64 index 20g+q mod 32 is a permutation).
// ---------------------------------------------------------------------------
#define GBM 128
#define GBN 256
#define GBK 32
#define GSTAGES 3
#define NCHUNK (D_MODEL / GBK)              // 64
#define ASTR 40                             // padded row stride (floats)
#define A_TILE_F (GBM * ASTR)               // 5120 floats
#define B_TILE_F (GBN * ASTR)               // 10240 floats
#define STAGE_F  (A_TILE_F + B_TILE_F)      // 15360 floats
#define GEMM_SMEM_BYTES (GSTAGES * STAGE_F * 4)   // 184320 B

__global__ void __launch_bounds__(256, 1) gemm_bf16x3(
    const float* __restrict__ A, const float* __restrict__ B,
    float* __restrict__ C)
{
    extern __shared__ float sm[];
    const int t  = threadIdx.x;
    const int w  = t >> 5;
    const int l  = t & 31;
    const int g  = l >> 2;        // group id (0..7)
    const int q  = l & 3;         // quad id  (0..3)
    const int wm = w >> 2;        // warp row (0..1) -> 64 rows
    const int wn = w & 3;         // warp col (0..3) -> 64 cols
    const int bm = blockIdx.y * GBM;
    const int bn = blockIdx.x * GBN;

    float acc[4][8][4];
#pragma unroll
    for (int mi = 0; mi < 4; mi++)
#pragma unroll
        for (int ni = 0; ni < 8; ni++)
#pragma unroll
            for (int c = 0; c < 4; c++) acc[mi][ni][c] = 0.0f;

    auto load_stage = [&](int s, int kc) {
        float* sA = sm + s * STAGE_F;
        float* sB = sA + A_TILE_F;
#pragma unroll
        for (int i = 0; i < 4; i++) {
            const int idx = i * 256 + t, r = idx >> 3, c16 = idx & 7;
            cp_async16(smem_u32(sA + r * ASTR + c16 * 4),
                       A + (size_t)(bm + r) * D_MODEL + kc + c16 * 4);
        }
#pragma unroll
        for (int i = 0; i < 8; i++) {
            const int idx = i * 256 + t, r = idx >> 3, c16 = idx & 7;
            cp_async16(smem_u32(sB + r * ASTR + c16 * 4),
                       B + (size_t)(bn + r) * D_MODEL + kc + c16 * 4);
        }
    };

#pragma unroll
    for (int s = 0; s < GSTAGES - 1; s++) { load_stage(s, s * GBK); cp_commit(); }

    for (int c = 0; c < NCHUNK; c++) {
        __syncthreads();
        const int lc = c + GSTAGES - 1;
        if (lc < NCHUNK) load_stage(lc % GSTAGES, lc * GBK);
        cp_commit();
        cp_wait<GSTAGES - 2>();
        __syncthreads();

        const float* sA = sm + (c % GSTAGES) * STAGE_F + (wm * 64) * ASTR;
        const float* sB = sm + (c % GSTAGES) * STAGE_F + A_TILE_F + (wn * 64) * ASTR;

#pragma unroll
        for (int ks = 0; ks < 2; ks++) {
            const int k0 = ks * 16 + 2 * q;   // covers k0..k0+1 and k0+8..k0+9

            // B fragments for all 8 n-tiles
            uint32_t bhi[8][2], blo[8][2];
#pragma unroll
            for (int ni = 0; ni < 8; ni++) {
                const int nrow = (ni * 8 + g) * ASTR;
                const float2 v0 = *(const float2*)&sB[nrow + k0];
                const float2 v1 = *(const float2*)&sB[nrow + k0 + 8];
                split2(v0, bhi[ni][0], blo[ni][0]);
                split2(v1, bhi[ni][1], blo[ni][1]);
            }

#pragma unroll
            for (int mi = 0; mi < 4; mi++) {
                const int r0 = (mi * 16 + g) * ASTR;
                const int r1 = (mi * 16 + g + 8) * ASTR;
                const float2 v00 = *(const float2*)&sA[r0 + k0];
                const float2 v10 = *(const float2*)&sA[r1 + k0];
                const float2 v01 = *(const float2*)&sA[r0 + k0 + 8];
                const float2 v11 = *(const float2*)&sA[r1 + k0 + 8];
                uint32_t ahi[4], alo[4];
                split2(v00, ahi[0], alo[0]);
                split2(v10, ahi[1], alo[1]);
                split2(v01, ahi[2], alo[2]);
                split2(v11, ahi[3], alo[3]);
#pragma unroll
                for (int ni = 0; ni < 8; ni++) {
                    mma_bf16(acc[mi][ni], ahi, bhi[ni]);
                    mma_bf16(acc[mi][ni], alo, bhi[ni]);
                    mma_bf16(acc[mi][ni], ahi, blo[ni]);
                }
            }
        }
    }

    // epilogue: direct STG.64 from accumulators (m16n8k16 C layout == m16n8k8)
#pragma unroll
    for (int mi = 0; mi < 4; mi++) {
        const int r0 = bm + wm * 64 + mi * 16 + g;
#pragma unroll
        for (int ni = 0; ni < 8; ni++) {
            const int col = bn + wn * 64 + ni * 8 + q * 2;
            *(float2*)&C[(size_t)r0 * D_MODEL + col] =
                make_float2(acc[mi][ni][0], acc[mi][ni][1]);
            *(float2*)&C[(size_t)(r0 + 8) * D_MODEL + col] =
                make_float2(acc[mi][ni][2], acc[mi][ni][3]);
        }
    }
}

// ---------------------------------------------------------------------------
// Flash attention (causal), SIMT — unchanged from R1.
// ---------------------------------------------------------------------------
#define QS_STRIDE 128
#define KS_STRIDE 132
#define VS_STRIDE 132
#define PS_STRIDE 66
#define SM_QS 0
#define SM_KS (SM_QS + 64 * QS_STRIDE)
#define SM_VS (SM_KS + 64 * KS_STRIDE)
#define SM_PS (SM_VS + 64 * VS_STRIDE)
#define ATT_SMEM_FLOATS (SM_PS + 64 * PS_STRIDE)
#define ATT_SMEM_BYTES  (ATT_SMEM_FLOATS * 4)
#define NEG_BIG (-1.0e30f)

__global__ void __launch_bounds__(256) attn_kernel(
    const float* __restrict__ Q, const float* __restrict__ K,
    const float* __restrict__ V, float* __restrict__ O)
{
    extern __shared__ float sm[];
    float* Qs = sm + SM_QS;
    float* Ks = sm + SM_KS;
    float* Vs = sm + SM_VS;
    float* Ps = sm + SM_PS;

    const int t  = threadIdx.x;
    const int w  = t >> 5;
    const int l  = t & 31;
    const int bh = blockIdx.y;
    const int b  = bh >> 4;
    const int h  = bh & 15;
    const int mt = blockIdx.x;
    const size_t base = ((size_t)b * SEQ) * D_MODEL + (size_t)h * DHEAD;
    const float scale = 0.088388347648318447f;

#pragma unroll
    for (int it = 0; it < 8; it++) {
        const int i  = it * 256 + t;
        const int r  = i >> 5;
        const int c4 = (i & 31) * 4;
        *(float4*)&Qs[r * QS_STRIDE + c4] =
            *(const float4*)(Q + base + (size_t)(mt * 64 + r) * D_MODEL + c4);
    }

    float m_i[8], l_i[8], acc[8][4];
#pragma unroll
    for (int i = 0; i < 8; i++) {
        m_i[i] = NEG_BIG; l_i[i] = 0.0f;
        acc[i][0] = acc[i][1] = acc[i][2] = acc[i][3] = 0.0f;
    }

    const int r0 = w * 8;

    for (int nt = 0; nt <= mt; nt++) {
        __syncthreads();
#pragma unroll
        for (int it = 0; it < 8; it++) {
            const int i  = it * 256 + t;
            const int r  = i >> 5;
            const int c4 = (i & 31) * 4;
            const size_t goff = base + (size_t)(nt * 64 + r) * D_MODEL + c4;
            *(float4*)&Ks[r * KS_STRIDE + c4] = *(const float4*)(K + goff);
            *(float4*)&Vs[r * VS_STRIDE + c4] = *(const float4*)(V + goff);
        }
        __syncthreads();

        float s0[8], s1[8];
#pragma unroll
        for (int i = 0; i < 8; i++) { s0[i] = 0.0f; s1[i] = 0.0f; }
#pragma unroll 4
        for (int k4 = 0; k4 < 32; k4++) {
            const float4 kv0 = *(const float4*)&Ks[l * KS_STRIDE + k4 * 4];
            const float4 kv1 = *(const float4*)&Ks[(32 + l) * KS_STRIDE + k4 * 4];
#pragma unroll
            for (int i = 0; i < 8; i++) {
                const float4 qv = *(const float4*)&Qs[(r0 + i) * QS_STRIDE + k4 * 4];
                s0[i] += qv.x * kv0.x + qv.y * kv0.y + qv.z * kv0.z + qv.w * kv0.w;
                s1[i] += qv.x * kv1.x + qv.y * kv1.y + qv.z * kv1.z + qv.w * kv1.w;
            }
        }

        const bool diag = (nt == mt);
#pragma unroll
        for (int i = 0; i < 8; i++) {
            const int qg = mt * 64 + r0 + i;
            float sv0 = s0[i] * scale;
            float sv1 = s1[i] * scale;
            if (diag) {
                if (nt * 64 + l      > qg) sv0 = NEG_BIG;
                if (nt * 64 + 32 + l > qg) sv1 = NEG_BIG;
            }
            float mx = fmaxf(sv0, sv1);
#pragma unroll
            for (int off = 16; off > 0; off >>= 1)
                mx = fmaxf(mx, __shfl_xor_sync(0xffffffffu, mx, off));
            const float mnew  = fmaxf(m_i[i], mx);
            const float alpha = __expf(m_i[i] - mnew);
            const float p0 = __expf(sv0 - mnew);
            const float p1 = __expf(sv1 - mnew);
            float rs = p0 + p1;
#pragma unroll
            for (int off = 16; off > 0; off >>= 1)
                rs += __shfl_xor_sync(0xffffffffu, rs, off);
            l_i[i] = l_i[i] * alpha + rs;
            m_i[i] = mnew;
            acc[i][0] *= alpha; acc[i][1] *= alpha;
            acc[i][2] *= alpha; acc[i][3] *= alpha;
            Ps[(r0 + i) * PS_STRIDE + l]      = p0;
            Ps[(r0 + i) * PS_STRIDE + 32 + l] = p1;
        }
        __syncwarp();

#pragma unroll 4
        for (int c = 0; c < 64; c++) {
            const float4 vv = *(const float4*)&Vs[c * VS_STRIDE + l * 4];
#pragma unroll
            for (int i = 0; i < 8; i++) {
                const float p = Ps[(r0 + i) * PS_STRIDE + c];
                acc[i][0] += p * vv.x;
                acc[i][1] += p * vv.y;
                acc[i][2] += p * vv.z;
                acc[i][3] += p * vv.w;
            }
        }
        __syncwarp();
    }

#pragma unroll
    for (int i = 0; i < 8; i++) {
        const float inv = 1.0f / l_i[i];
        const int qg = mt * 64 + r0 + i;
        float4 o = make_float4(acc[i][0] * inv, acc[i][1] * inv,
                               acc[i][2] * inv, acc[i][3] * inv);
        *(float4*)(O + base + (size_t)qg * D_MODEL + l * 4) = o;
    }
}

// ---------------------------------------------------------------------------
// Launcher
// ---------------------------------------------------------------------------
extern "C" void kernel_launch(void* const* d_in, const int* in_sizes, int n_in,
                              void* d_out, int out_size)
{
    const float* x  = (const float*)d_in[0];
    const float* Wq = (const float*)d_in[1];
    const float* Wk = (const float*)d_in[2];
    const float* Wv = (const float*)d_in[3];
    const float* Wo = (const float*)d_in[4];
    float* out = (float*)d_out;

    void *pQ, *pK, *pV, *pA;
    cudaGetSymbolAddress(&pQ, g_Q);
    cudaGetSymbolAddress(&pK, g_K);
    cudaGetSymbolAddress(&pV, g_V);
    cudaGetSymbolAddress(&pA, g_AO);

    cudaFuncSetAttribute(gemm_bf16x3,
                         cudaFuncAttributeMaxDynamicSharedMemorySize, GEMM_SMEM_BYTES);
    cudaFuncSetAttribute(attn_kernel,
                         cudaFuncAttributeMaxDynamicSharedMemorySize, ATT_SMEM_BYTES);

    const dim3 ggrid(D_MODEL / GBN, MROWS / GBM);        // (8, 64)
    gemm_bf16x3<<<ggrid, 256, GEMM_SMEM_BYTES>>>(x, Wq, (float*)pQ);
    gemm_bf16x3<<<ggrid, 256, GEMM_SMEM_BYTES>>>(x, Wk, (float*)pK);
    gemm_bf16x3<<<ggrid, 256, GEMM_SMEM_BYTES>>>(x, Wv, (float*)pV);

    const dim3 attn_grid(SEQ / 64, BATCH * NHEADS);      // (32, 64)
    attn_kernel<<<attn_grid, 256, ATT_SMEM_BYTES>>>(
        (const float*)pQ, (const float*)pK, (const float*)pV, (float*)pA);

    gemm_bf16x3<<<ggrid, 256, GEMM_SMEM_BYTES>>>((const float*)pA, Wo, out);
}

// round 7
// speedup vs baseline: 1.7564x; 1.0459x over previous
#include <cuda_runtime.h>
#include <cuda_bf16.h>
#include <cstdint>
#include <math.h>

// ============================================================================
// StandardAttention, B=4, S=2048, D=2048, H=16, Dh=128, fp32.
// R7: R6 with the K-swizzle READ decode fixed: physical col p of row r holds
//     logical chunk p^(r&31); reading sc=(k4^l) on rows l and 32+l yields
//     logical k4 -> Q must be indexed at k4 (broadcast), NOT k4^l (R6 bug).
// ============================================================================

#define D_MODEL 2048
#define SEQ     2048
#define BATCH   4
#define NHEADS  16
#define DHEAD   128
#define MROWS   (BATCH * SEQ)          // 8192

__device__ float g_Q [ (size_t)BATCH * SEQ * D_MODEL ];
__device__ float g_K [ (size_t)BATCH * SEQ * D_MODEL ];
__device__ float g_V [ (size_t)BATCH * SEQ * D_MODEL ];
__device__ float g_AO[ (size_t)BATCH * SEQ * D_MODEL ];

// ---------------------------------------------------------------------------
// Helpers
// ---------------------------------------------------------------------------
__device__ __forceinline__ uint32_t smem_u32(const void* p) {
    uint32_t a;
    asm("{ .reg .u64 t; cvta.to.shared.u64 t, %1; cvt.u32.u64 %0, t; }"
        : "=r"(a) : "l"(p));
    return a;
}
__device__ __forceinline__ void cp_async16(uint32_t dst, const void* src) {
    asm volatile("cp.async.cg.shared.global [%0], [%1], 16;"
                 :: "r"(dst), "l"(src) : "memory");
}
__device__ __forceinline__ void cp_commit() {
    asm volatile("cp.async.commit_group;" ::: "memory");
}
template<int N> __device__ __forceinline__ void cp_wait() {
    asm volatile("cp.async.wait_group %0;" :: "n"(N) : "memory");
}

__device__ __forceinline__ void mma_bf16(float* d, const uint32_t* a,
                                         const uint32_t* b) {
    asm volatile(
        "mma.sync.aligned.m16n8k16.row.col.f32.bf16.bf16.f32 "
        "{%0,%1,%2,%3}, {%4,%5,%6,%7}, {%8,%9}, {%0,%1,%2,%3};"
        : "+f"(d[0]), "+f"(d[1]), "+f"(d[2]), "+f"(d[3])
        : "r"(a[0]), "r"(a[1]), "r"(a[2]), "r"(a[3]), "r"(b[0]), "r"(b[1]));
}

__device__ __forceinline__ void split2(float2 v, uint32_t& hi, uint32_t& lo) {
    asm("cvt.rn.bf16x2.f32 %0, %1, %2;" : "=r"(hi) : "f"(v.y), "f"(v.x));
    const float hx = __uint_as_float(hi << 16);
    const float hy = __uint_as_float(hi & 0xffff0000u);
    const float lx = v.x - hx;
    const float ly = v.y - hy;
    asm("cvt.rn.bf16x2.f32 %0, %1, %2;" : "=r"(lo) : "f"(ly), "f"(lx));
}

// ---------------------------------------------------------------------------
// bf16x3 GEMM-NT: C[8192,2048] = A[8192,2048] * B[2048,2048]^T (fp32 I/O)
// CTA 128x256, BK=32, 3-stage cp.async. 8 warps, warp tile 64x64.
// ---------------------------------------------------------------------------
#define GBM 128
#define GBN 256
#define GBK 32
#define GSTAGES 3
#define NCHUNK (D_MODEL / GBK)              // 64
#define ASTR 40
#define A_TILE_F (GBM * ASTR)
#define B_TILE_F (GBN * ASTR)
#define STAGE_F  (A_TILE_F + B_TILE_F)
#define GEMM_SMEM_BYTES (GSTAGES * STAGE_F * 4)

__global__ void __launch_bounds__(256, 1) gemm_bf16x3(
    const float* __restrict__ A, const float* __restrict__ B,
    float* __restrict__ C)
{
    extern __shared__ float sm[];
    const int t  = threadIdx.x;
    const int w  = t >> 5;
    const int l  = t & 31;
    const int g  = l >> 2;
    const int q  = l & 3;
    const int wm = w >> 2;
    const int wn = w & 3;
    const int bm = blockIdx.y * GBM;
    const int bn = blockIdx.x * GBN;

    float acc[4][8][4];
#pragma unroll
    for (int mi = 0; mi < 4; mi++)
#pragma unroll
        for (int ni = 0; ni < 8; ni++)
#pragma unroll
            for (int c = 0; c < 4; c++) acc[mi][ni][c] = 0.0f;

    auto load_stage = [&](int s, int kc) {
        float* sA = sm + s * STAGE_F;
        float* sB = sA + A_TILE_F;
#pragma unroll
        for (int i = 0; i < 4; i++) {
            const int idx = i * 256 + t, r = idx >> 3, c16 = idx & 7;
            cp_async16(smem_u32(sA + r * ASTR + c16 * 4),
                       A + (size_t)(bm + r) * D_MODEL + kc + c16 * 4);
        }
#pragma unroll
        for (int i = 0; i < 8; i++) {
            const int idx = i * 256 + t, r = idx >> 3, c16 = idx & 7;
            cp_async16(smem_u32(sB + r * ASTR + c16 * 4),
                       B + (size_t)(bn + r) * D_MODEL + kc + c16 * 4);
        }
    };

#pragma unroll
    for (int s = 0; s < GSTAGES - 1; s++) { load_stage(s, s * GBK); cp_commit(); }

    for (int c = 0; c < NCHUNK; c++) {
        __syncthreads();
        const int lc = c + GSTAGES - 1;
        if (lc < NCHUNK) load_stage(lc % GSTAGES, lc * GBK);
        cp_commit();
        cp_wait<GSTAGES - 2>();
        __syncthreads();

        const float* sA = sm + (c % GSTAGES) * STAGE_F + (wm * 64) * ASTR;
        const float* sB = sm + (c % GSTAGES) * STAGE_F + A_TILE_F + (wn * 64) * ASTR;

#pragma unroll
        for (int ks = 0; ks < 2; ks++) {
            const int k0 = ks * 16 + 2 * q;

            uint32_t bhi[8][2], blo[8][2];
#pragma unroll
            for (int ni = 0; ni < 8; ni++) {
                const int nrow = (ni * 8 + g) * ASTR;
                const float2 v0 = *(const float2*)&sB[nrow + k0];
                const float2 v1 = *(const float2*)&sB[nrow + k0 + 8];
                split2(v0, bhi[ni][0], blo[ni][0]);
                split2(v1, bhi[ni][1], blo[ni][1]);
            }

#pragma unroll
            for (int mi = 0; mi < 4; mi++) {
                const int r0 = (mi * 16 + g) * ASTR;
                const int r1 = (mi * 16 + g + 8) * ASTR;
                const float2 v00 = *(const float2*)&sA[r0 + k0];
                const float2 v10 = *(const float2*)&sA[r1 + k0];
                const float2 v01 = *(const float2*)&sA[r0 + k0 + 8];
                const float2 v11 = *(const float2*)&sA[r1 + k0 + 8];
                uint32_t ahi[4], alo[4];
                split2(v00, ahi[0], alo[0]);
                split2(v10, ahi[1], alo[1]);
                split2(v01, ahi[2], alo[2]);
                split2(v11, ahi[3], alo[3]);
#pragma unroll
                for (int ni = 0; ni < 8; ni++) mma_bf16(acc[mi][ni], ahi, bhi[ni]);
#pragma unroll
                for (int ni = 0; ni < 8; ni++) mma_bf16(acc[mi][ni], alo, bhi[ni]);
#pragma unroll
                for (int ni = 0; ni < 8; ni++) mma_bf16(acc[mi][ni], ahi, blo[ni]);
            }
        }
    }

#pragma unroll
    for (int mi = 0; mi < 4; mi++) {
        const int r0 = bm + wm * 64 + mi * 16 + g;
#pragma unroll
        for (int ni = 0; ni < 8; ni++) {
            const int col = bn + wn * 64 + ni * 8 + q * 2;
            *(float2*)&C[(size_t)r0 * D_MODEL + col] =
                make_float2(acc[mi][ni][0], acc[mi][ni][1]);
            *(float2*)&C[(size_t)(r0 + 8) * D_MODEL + col] =
                make_float2(acc[mi][ni][2], acc[mi][ni][3]);
        }
    }
}

// ---------------------------------------------------------------------------
// Flash attention (causal), SIMT. smem = 114,944 B -> 2 CTAs/SM.
//  Q: 64x128 plain.  K: 64x128, physical col = logical ^ (row&31).
//  V: 64x128 plain.  P: 64 cols, stride 65.
// ---------------------------------------------------------------------------
#define QS_STRIDE 128
#define KS_STRIDE 128
#define VS_STRIDE 128
#define PS_STRIDE 65
#define SM_QS 0
#define SM_KS (SM_QS + 64 * QS_STRIDE)
#define SM_VS (SM_KS + 64 * KS_STRIDE)
#define SM_PS (SM_VS + 64 * VS_STRIDE)
#define ATT_SMEM_FLOATS (SM_PS + 64 * PS_STRIDE)   // 28736
#define ATT_SMEM_BYTES  (ATT_SMEM_FLOATS * 4)      // 114944
#define NEG_BIG (-1.0e30f)

__global__ void __launch_bounds__(256, 2) attn_kernel(
    const float* __restrict__ Q, const float* __restrict__ K,
    const float* __restrict__ V, float* __restrict__ O)
{
    extern __shared__ float sm[];
    float* Qs = sm + SM_QS;
    float* Ks = sm + SM_KS;
    float* Vs = sm + SM_VS;
    float* Ps = sm + SM_PS;

    const int t  = threadIdx.x;
    const int w  = t >> 5;
    const int l  = t & 31;
    const int bh = blockIdx.y;
    const int b  = bh >> 4;
    const int h  = bh & 15;
    const int mt = blockIdx.x;
    const size_t base = ((size_t)b * SEQ) * D_MODEL + (size_t)h * DHEAD;
    const float scale = 0.088388347648318447f;

#pragma unroll
    for (int it = 0; it < 8; it++) {
        const int i  = it * 256 + t;
        const int r  = i >> 5;
        const int c4 = (i & 31);
        *(float4*)&Qs[r * QS_STRIDE + c4 * 4] =
            *(const float4*)(Q + base + (size_t)(mt * 64 + r) * D_MODEL + c4 * 4);
    }

    float m_i[8], l_i[8], acc[8][4];
#pragma unroll
    for (int i = 0; i < 8; i++) {
        m_i[i] = NEG_BIG; l_i[i] = 0.0f;
        acc[i][0] = acc[i][1] = acc[i][2] = acc[i][3] = 0.0f;
    }

    const int r0 = w * 8;

    for (int nt = 0; nt <= mt; nt++) {
        __syncthreads();
#pragma unroll
        for (int it = 0; it < 8; it++) {
            const int i  = it * 256 + t;
            const int r  = i >> 5;
            const int c4 = (i & 31);
            const size_t goff = base + (size_t)(nt * 64 + r) * D_MODEL + c4 * 4;
            // K: store logical chunk c4 at physical col c4^(r&31)
            *(float4*)&Ks[r * KS_STRIDE + ((c4 ^ (r & 31)) * 4)] =
                *(const float4*)(K + goff);
            *(float4*)&Vs[r * VS_STRIDE + c4 * 4] = *(const float4*)(V + goff);
        }
        __syncthreads();

        float s0[8], s1[8];
#pragma unroll
        for (int i = 0; i < 8; i++) { s0[i] = 0.0f; s1[i] = 0.0f; }
#pragma unroll 4
        for (int k4 = 0; k4 < 32; k4++) {
            // physical col (k4^l) of rows l and 32+l both hold LOGICAL chunk k4
            const int sc = (k4 ^ l) * 4;
            const float4 kv0 = *(const float4*)&Ks[l * KS_STRIDE + sc];
            const float4 kv1 = *(const float4*)&Ks[(32 + l) * KS_STRIDE + sc];
            const int kk = k4 * 4;          // Q at logical k4 (broadcast)
#pragma unroll
            for (int i = 0; i < 8; i++) {
                const float4 qv = *(const float4*)&Qs[(r0 + i) * QS_STRIDE + kk];
                s0[i] += qv.x * kv0.x + qv.y * kv0.y + qv.z * kv0.z + qv.w * kv0.w;
                s1[i] += qv.x * kv1.x + qv.y * kv1.y + qv.z * kv1.z + qv.w * kv1.w;
            }
        }

        const bool diag = (nt == mt);
#pragma unroll
        for (int i = 0; i < 8; i++) {
            const int qg = mt * 64 + r0 + i;
            float sv0 = s0[i] * scale;
            float sv1 = s1[i] * scale;
            if (diag) {
                if (nt * 64 + l      > qg) sv0 = NEG_BIG;
                if (nt * 64 + 32 + l > qg) sv1 = NEG_BIG;
            }
            float mx = fmaxf(sv0, sv1);
#pragma unroll
            for (int off = 16; off > 0; off >>= 1)
                mx = fmaxf(mx, __shfl_xor_sync(0xffffffffu, mx, off));
            const float mnew  = fmaxf(m_i[i], mx);
            const float alpha = __expf(m_i[i] - mnew);
            const float p0 = __expf(sv0 - mnew);
            const float p1 = __expf(sv1 - mnew);
            float rs = p0 + p1;
#pragma unroll
            for (int off = 16; off > 0; off >>= 1)
                rs += __shfl_xor_sync(0xffffffffu, rs, off);
            l_i[i] = l_i[i] * alpha + rs;
            m_i[i] = mnew;
            acc[i][0] *= alpha; acc[i][1] *= alpha;
            acc[i][2] *= alpha; acc[i][3] *= alpha;
            Ps[(r0 + i) * PS_STRIDE + l]      = p0;
            Ps[(r0 + i) * PS_STRIDE + 32 + l] = p1;
        }
        __syncwarp();

#pragma unroll 4
        for (int c = 0; c < 64; c++) {
            const float4 vv = *(const float4*)&Vs[c * VS_STRIDE + l * 4];
#pragma unroll
            for (int i = 0; i < 8; i++) {
                const float p = Ps[(r0 + i) * PS_STRIDE + c];
                acc[i][0] += p * vv.x;
                acc[i][1] += p * vv.y;
                acc[i][2] += p * vv.z;
                acc[i][3] += p * vv.w;
            }
        }
        __syncwarp();
    }

#pragma unroll
    for (int i = 0; i < 8; i++) {
        const float inv = 1.0f / l_i[i];
        const int qg = mt * 64 + r0 + i;
        float4 o = make_float4(acc[i][0] * inv, acc[i][1] * inv,
                               acc[i][2] * inv, acc[i][3] * inv);
        *(float4*)(O + base + (size_t)qg * D_MODEL + l * 4) = o;
    }
}

// ---------------------------------------------------------------------------
// Launcher
// ---------------------------------------------------------------------------
extern "C" void kernel_launch(void* const* d_in, const int* in_sizes, int n_in,
                              void* d_out, int out_size)
{
    const float* x  = (const float*)d_in[0];
    const float* Wq = (const float*)d_in[1];
    const float* Wk = (const float*)d_in[2];
    const float* Wv = (const float*)d_in[3];
    const float* Wo = (const float*)d_in[4];
    float* out = (float*)d_out;

    void *pQ, *pK, *pV, *pA;
    cudaGetSymbolAddress(&pQ, g_Q);
    cudaGetSymbolAddress(&pK, g_K);
    cudaGetSymbolAddress(&pV, g_V);
    cudaGetSymbolAddress(&pA, g_AO);

    cudaFuncSetAttribute(gemm_bf16x3,
                         cudaFuncAttributeMaxDynamicSharedMemorySize, GEMM_SMEM_BYTES);
    cudaFuncSetAttribute(attn_kernel,
                         cudaFuncAttributeMaxDynamicSharedMemorySize, ATT_SMEM_BYTES);

    const dim3 ggrid(D_MODEL / GBN, MROWS / GBM);        // (8, 64)
    gemm_bf16x3<<<ggrid, 256, GEMM_SMEM_BYTES>>>(x, Wq, (float*)pQ);
    gemm_bf16x3<<<ggrid, 256, GEMM_SMEM_BYTES>>>(x, Wk, (float*)pK);
    gemm_bf16x3<<<ggrid, 256, GEMM_SMEM_BYTES>>>(x, Wv, (float*)pV);

    const dim3 attn_grid(SEQ / 64, BATCH * NHEADS);      // (32, 64)
    attn_kernel<<<attn_grid, 256, ATT_SMEM_BYTES>>>(
        (const float*)pQ, (const float*)pK, (const float*)pV, (float*)pA);

    gemm_bf16x3<<<ggrid, 256, GEMM_SMEM_BYTES>>>((const float*)pA, Wo, out);
}